// round 3
// baseline (speedup 1.0000x reference)
#include <cuda_runtime.h>
#include <math.h>

// ============================================================================
// DGISubgraphCL: full pipeline on device.
// Inputs (metadata order): feat[N,64] f32, W_enc[64,64] f32, W_disc[64,64] f32,
//   src[E] i32, dst[E] i32, perm_neg[N] i32, perm1[N] i32, perm2[N] i32.
// Output: scalar f32 loss.
// ============================================================================

#define N_MAX 131072
#define E_MAX (N_MAX * 17)
#define HIST_BINS 15001
#define MAX_ITERS 16

// ---- device scratch (allocation-free rule: __device__ globals) ----
__device__ int g_rowptr[N_MAX + 1];
__device__ int g_cnt[N_MAX];
__device__ int g_cursor[N_MAX];
__device__ int g_colidx[E_MAX];
__device__ int g_hop[2][N_MAX];
__device__ int g_invperm[N_MAX];
__device__ unsigned char g_keep[N_MAX];
__device__ int g_hist[HIST_BINS];
__device__ float g_hpos[N_MAX * 64];
__device__ float g_hneg[N_MAX * 64];
__device__ double g_summary[64];
__device__ float g_v[2][64];
__device__ double g_loss[4];

// BFS / selection control state
__device__ int g_cur, g_done, g_hc, g_cntPrev, g_cntAcc;
__device__ unsigned long long g_seedkey;
__device__ int g_hstar, g_rrem, g_pstar;

// ============================================================================
// helpers
// ============================================================================

__device__ __forceinline__ float softplusf(float x) {
    // log(1+exp(x)) = max(x,0) + log1p(exp(-|x|))
    return fmaxf(x, 0.f) + log1pf(expf(-fabsf(x)));
}

// inclusive block scan, blockDim.x == 1024 required
__device__ __forceinline__ int blockScanInc(int v, int* sWarp) {
    int lane = threadIdx.x & 31;
    int wid = threadIdx.x >> 5;
#pragma unroll
    for (int off = 1; off < 32; off <<= 1) {
        int t = __shfl_up_sync(0xffffffffu, v, off);
        if (lane >= off) v += t;
    }
    if (lane == 31) sWarp[wid] = v;
    __syncthreads();
    if (wid == 0) {
        int w = sWarp[lane];
#pragma unroll
        for (int off = 1; off < 32; off <<= 1) {
            int t = __shfl_up_sync(0xffffffffu, w, off);
            if (lane >= off) w += t;
        }
        sWarp[lane] = w;
    }
    __syncthreads();
    return v + (wid ? sWarp[wid - 1] : 0);
}

// ============================================================================
// CSR build (group edges by dst)
// ============================================================================

__global__ void zero_init_kernel(int n) {
    int i = blockIdx.x * blockDim.x + threadIdx.x;
    if (i < n) { g_cnt[i] = 0; g_cursor[i] = 0; }
    if (i < 4) g_loss[i] = 0.0;
}

__global__ void count_dst_kernel(const int* __restrict__ dst, int e) {
    int i = blockIdx.x * blockDim.x + threadIdx.x;
    if (i < e) atomicAdd(&g_cnt[dst[i]], 1);
}

__global__ void scan_counts_kernel(int n) {
    __shared__ int sWarp[32];
    __shared__ int sRun, sTot;
    int tid = threadIdx.x;
    if (tid == 0) sRun = 0;
    __syncthreads();
    for (int base = 0; base < n; base += 1024) {
        int i = base + tid;
        int v = (i < n) ? g_cnt[i] : 0;
        int incl = blockScanInc(v, sWarp);
        if (i < n) g_rowptr[i] = sRun + incl - v;
        if (tid == 1023) sTot = incl;
        __syncthreads();
        if (tid == 0) sRun += sTot;
        __syncthreads();
    }
    if (tid == 0) g_rowptr[n] = sRun;
}

__global__ void scatter_kernel(const int* __restrict__ src, const int* __restrict__ dst, int e) {
    int i = blockIdx.x * blockDim.x + threadIdx.x;
    if (i < e) {
        int d = dst[i];
        int p = atomicAdd(&g_cursor[d], 1);
        g_colidx[g_rowptr[d] + p] = src[i];
    }
}

// ============================================================================
// Full GCN (all-ones edge mask): h = relu((agg/deg) @ W), written to hpos/hneg.
// Warp per node, 2 columns per lane, W staged in shared.
// ============================================================================

__global__ void gcn_kernel(const float* __restrict__ feat, const float* __restrict__ Wenc,
                           const int* __restrict__ permneg, int n, int mode) {
    __shared__ float sW[4096];
    __shared__ float sx[8][64];
    int tid = threadIdx.x;
    for (int j = tid; j < 4096; j += blockDim.x) sW[j] = Wenc[j];
    __syncthreads();
    int warp = tid >> 5, lane = tid & 31;
    float* out = mode ? g_hneg : g_hpos;
    for (int node = blockIdx.x * 8 + warp; node < n; node += gridDim.x * 8) {
        int s0 = g_rowptr[node], s1 = g_rowptr[node + 1];
        float a0 = 0.f, a1 = 0.f;
        for (int e = s0; e < s1; e++) {
            int s = g_colidx[e];
            int r = permneg ? permneg[s] : s;
            float2 f = *reinterpret_cast<const float2*>(feat + (size_t)r * 64 + 2 * lane);
            a0 += f.x; a1 += f.y;
        }
        float invd = 1.f / (float)max(s1 - s0, 1);
        sx[warp][2 * lane] = a0 * invd;
        sx[warp][2 * lane + 1] = a1 * invd;
        __syncwarp();
        float o0 = 0.f, o1 = 0.f;
#pragma unroll
        for (int kk = 0; kk < 64; kk++) {
            float xv = sx[warp][kk];
            o0 += xv * sW[kk * 64 + 2 * lane];
            o1 += xv * sW[kk * 64 + 2 * lane + 1];
        }
        float2 r2 = make_float2(fmaxf(o0, 0.f), fmaxf(o1, 0.f));
        *reinterpret_cast<float2*>(out + (size_t)node * 64 + 2 * lane) = r2;
        __syncwarp();
    }
}

// ============================================================================
// BFS (exact replication of reference while-loop, double-buffered int hops)
// ============================================================================

__global__ void bfs_init_kernel(const int* __restrict__ perm, int n) {
    int i = blockIdx.x * blockDim.x + threadIdx.x;
    int root = perm[0];
    if (i < n) {
        g_hop[0][i] = (i == root) ? 0 : n;
        g_invperm[perm[i]] = i;
    }
    if (i < HIST_BINS) g_hist[i] = 0;
    if (i < 64) g_summary[i] = 0.0;
    if (i == 0) {
        g_cur = 0; g_done = 0; g_hc = 0;
        g_cntPrev = 1; g_cntAcc = 0;
        g_seedkey = ~0ull;
    }
}

__global__ void bfs_relax_kernel(const int* __restrict__ perm, int n) {
    if (g_done) return;
    int cur = g_cur;
    const int* __restrict__ ho = g_hop[cur];
    int* __restrict__ hn = g_hop[cur ^ 1];
    int i = blockIdx.x * blockDim.x + threadIdx.x;
    int reached = 0;
    unsigned long long key = ~0ull;
    if (i < n) {
        int h = ho[i];
        int s0 = g_rowptr[i], s1 = g_rowptr[i + 1];
        for (int e = s0; e < s1; e++) {
            int s = g_colidx[e];
            int c = ho[s] + (s != i);  // self-loop weight 0
            h = min(h, c);
        }
        hn[i] = h;
        if (h < n) reached = 1;
        else key = ((unsigned long long)(unsigned)perm[i] << 32) | (unsigned)i;
    }
#pragma unroll
    for (int off = 16; off; off >>= 1) {
        reached += __shfl_down_sync(0xffffffffu, reached, off);
        unsigned long long ok = __shfl_down_sync(0xffffffffu, key, off);
        key = (ok < key) ? ok : key;
    }
    if ((threadIdx.x & 31) == 0) {
        if (reached) atomicAdd(&g_cntAcc, reached);
        if (key != ~0ull) atomicMin(&g_seedkey, key);
    }
}

__global__ void bfs_step_kernel(int n, int target) {
    if (g_done) return;
    int hc = g_hc + 1;
    g_hc = hc;
    int cur = g_cur ^ 1;  // buffer just written
    int cnt = g_cntAcc;
    if (cnt == g_cntPrev) {
        unsigned long long k = g_seedkey;
        if (k != ~0ull) {
            int idx = (int)(unsigned)(k & 0xffffffffull);
            g_hop[cur][idx] = hc;
            cnt += 1;
        }
    }
    g_cntPrev = cnt;
    g_cur = cur;
    g_cntAcc = 0;
    g_seedkey = ~0ull;
    if (cnt > target) g_done = 1;
}

// ============================================================================
// Top-k selection by (clipped hop, perm); exact, sort-free.
// ============================================================================

__global__ void hist_kernel(int n) {
    __shared__ int sh[64];
    __shared__ int shTop;
    int tid = threadIdx.x;
    if (tid < 64) sh[tid] = 0;
    if (tid == 0) shTop = 0;
    __syncthreads();
    int cur = g_cur;
    int i = blockIdx.x * blockDim.x + tid;
    if (i < n) {
        int hv = min(g_hop[cur][i], 15000);
        if (hv < 64) atomicAdd(&sh[hv], 1);
        else if (hv == 15000) atomicAdd(&shTop, 1);
        else atomicAdd(&g_hist[hv], 1);
    }
    __syncthreads();
    if (tid < 64 && sh[tid]) atomicAdd(&g_hist[tid], sh[tid]);
    if (tid == 0 && shTop) atomicAdd(&g_hist[15000], shTop);
}

__global__ void find_hstar_kernel(int target) {
    __shared__ int sWarp[32];
    __shared__ int sRun, sTot, sDone;
    int tid = threadIdx.x;
    if (tid == 0) { sRun = 0; sDone = 0; }
    __syncthreads();
    for (int base = 0; base < HIST_BINS; base += 1024) {
        if (sDone) break;
        int h = base + tid;
        int v = (h < HIST_BINS) ? g_hist[h] : 0;
        int incl = blockScanInc(v, sWarp);
        int P = sRun + incl;
        if (v > 0 && P >= target && P - v < target) {
            g_hstar = h;
            g_rrem = target - (P - v);
            sDone = 1;
        }
        if (tid == 1023) sTot = incl;
        __syncthreads();
        if (tid == 0) sRun += sTot;
        __syncthreads();
    }
}

__global__ void find_pstar_kernel(int n) {
    __shared__ int sWarp[32];
    __shared__ int sRun, sTot, sDone;
    int tid = threadIdx.x;
    if (tid == 0) { sRun = 0; sDone = 0; }
    __syncthreads();
    int cur = g_cur, hstar = g_hstar, rrem = g_rrem;
    const int* hop = g_hop[cur];
    for (int base = 0; base < n; base += 1024) {
        if (sDone) break;
        int v = base + tid;
        int pred = 0;
        if (v < n) {
            int j = g_invperm[v];
            pred = (min(hop[j], 15000) == hstar);
        }
        int incl = blockScanInc(pred, sWarp);
        int cum = sRun + incl;
        if (pred && cum == rrem) { g_pstar = v; sDone = 1; }
        if (tid == 1023) sTot = incl;
        __syncthreads();
        if (tid == 0) sRun += sTot;
        __syncthreads();
    }
}

__global__ void keep_kernel(const int* __restrict__ perm, int n) {
    int i = blockIdx.x * blockDim.x + threadIdx.x;
    if (i >= n) return;
    int cur = g_cur, hs = g_hstar, ps = g_pstar;
    int hv = min(g_hop[cur][i], 15000);
    g_keep[i] = (hv < hs) || (hv == hs && perm[i] <= ps);
}

// ============================================================================
// Masked GCN fused with summary accumulation (only kept dst rows matter).
// ============================================================================

__global__ void masked_gcn_kernel(const float* __restrict__ feat, const float* __restrict__ Wenc, int n) {
    __shared__ float sW[4096];
    __shared__ float sx[8][64];
    int tid = threadIdx.x;
    for (int j = tid; j < 4096; j += blockDim.x) sW[j] = Wenc[j];
    __syncthreads();
    int warp = tid >> 5, lane = tid & 31;
    double acc0 = 0.0, acc1 = 0.0;
    for (int node = blockIdx.x * 8 + warp; node < n; node += gridDim.x * 8) {
        if (!g_keep[node]) continue;
        int s0 = g_rowptr[node], s1 = g_rowptr[node + 1];
        float a0 = 0.f, a1 = 0.f;
        int cnt = 0;
        for (int e = s0; e < s1; e++) {
            int s = g_colidx[e];
            if (g_keep[s]) {
                float2 f = *reinterpret_cast<const float2*>(feat + (size_t)s * 64 + 2 * lane);
                a0 += f.x; a1 += f.y; cnt++;
            }
        }
        float invd = 1.f / (float)max(cnt, 1);
        sx[warp][2 * lane] = a0 * invd;
        sx[warp][2 * lane + 1] = a1 * invd;
        __syncwarp();
        float o0 = 0.f, o1 = 0.f;
#pragma unroll
        for (int kk = 0; kk < 64; kk++) {
            float xv = sx[warp][kk];
            o0 += xv * sW[kk * 64 + 2 * lane];
            o1 += xv * sW[kk * 64 + 2 * lane + 1];
        }
        acc0 += (double)fmaxf(o0, 0.f);
        acc1 += (double)fmaxf(o1, 0.f);
        __syncwarp();
    }
    atomicAdd(&g_summary[2 * lane], acc0);
    atomicAdd(&g_summary[2 * lane + 1], acc1);
}

__global__ void compute_v_kernel(const float* __restrict__ Wdisc, int p, int k) {
    __shared__ float ss[64];
    int tid = threadIdx.x;  // 64 threads
    double s = g_summary[tid] / (double)k;
    ss[tid] = (float)(1.0 / (1.0 + exp(-s)));
    __syncthreads();
    float v = 0.f;
#pragma unroll
    for (int b = 0; b < 64; b++) v += Wdisc[tid * 64 + b] * ss[b];
    g_v[p][tid] = v;
}

// ============================================================================
// Final BCE losses: both perms in a single pass over h_pos / h_neg.
// ============================================================================

__global__ void loss_kernel(int n) {
    __shared__ float sv0[64], sv1[64];
    int tid = threadIdx.x;
    if (tid < 64) { sv0[tid] = g_v[0][tid]; sv1[tid] = g_v[1][tid]; }
    __syncthreads();
    int warp = tid >> 5, lane = tid & 31;
    float v00 = sv0[2 * lane], v01 = sv0[2 * lane + 1];
    float v10 = sv1[2 * lane], v11 = sv1[2 * lane + 1];
    double l0 = 0, l1 = 0, l2 = 0, l3 = 0;
    for (int node = blockIdx.x * 8 + warp; node < n; node += gridDim.x * 8) {
        float2 hp = *reinterpret_cast<const float2*>(g_hpos + (size_t)node * 64 + 2 * lane);
        float2 hn = *reinterpret_cast<const float2*>(g_hneg + (size_t)node * 64 + 2 * lane);
        float p1 = hp.x * v00 + hp.y * v01;
        float p2 = hp.x * v10 + hp.y * v11;
        float q1 = hn.x * v00 + hn.y * v01;
        float q2 = hn.x * v10 + hn.y * v11;
#pragma unroll
        for (int off = 16; off; off >>= 1) {
            p1 += __shfl_down_sync(0xffffffffu, p1, off);
            p2 += __shfl_down_sync(0xffffffffu, p2, off);
            q1 += __shfl_down_sync(0xffffffffu, q1, off);
            q2 += __shfl_down_sync(0xffffffffu, q2, off);
        }
        if (lane == 0) {
            l0 += (double)softplusf(-p1);
            l1 += (double)softplusf(q1);
            l2 += (double)softplusf(-p2);
            l3 += (double)softplusf(q2);
        }
    }
    if (lane == 0) {
        atomicAdd(&g_loss[0], l0);
        atomicAdd(&g_loss[1], l1);
        atomicAdd(&g_loss[2], l2);
        atomicAdd(&g_loss[3], l3);
    }
}

__global__ void finalize_kernel(float* out, int n) {
    out[0] = (float)((g_loss[0] + g_loss[1] + g_loss[2] + g_loss[3]) / (double)n);
}

// ============================================================================
// launch
// ============================================================================

extern "C" void kernel_launch(void* const* d_in, const int* in_sizes, int n_in,
                              void* d_out, int out_size) {
    const float* feat = (const float*)d_in[0];
    const float* Wenc = (const float*)d_in[1];
    const float* Wdisc = (const float*)d_in[2];
    const int* src = (const int*)d_in[3];
    const int* dst = (const int*)d_in[4];
    const int* permneg = (const int*)d_in[5];
    const int* perm1 = (const int*)d_in[6];
    const int* perm2 = (const int*)d_in[7];

    int e = in_sizes[3];
    int n = in_sizes[5];
    int k = (int)((double)n * 0.8);  // int(n * KEEP_FRAC)

    const int T = 256;
    int nbN = (n + T - 1) / T;
    int nbE = (e + T - 1) / T;
    int nInit = (n > HIST_BINS) ? n : HIST_BINS;
    int nbI = (nInit + T - 1) / T;

    // CSR build (group by dst)
    zero_init_kernel<<<nbN, T>>>(n);
    count_dst_kernel<<<nbE, T>>>(dst, e);
    scan_counts_kernel<<<1, 1024>>>(n);
    scatter_kernel<<<nbE, T>>>(src, dst, e);

    // pos / neg GCN embeddings
    int gB = (n + 7) / 8;
    int gStride = gB < 2960 ? gB : 2960;
    gcn_kernel<<<gStride, 256>>>(feat, Wenc, nullptr, n, 0);
    gcn_kernel<<<gStride, 256>>>(feat, Wenc, permneg, n, 1);

    const int* perms[2] = {perm1, perm2};
    for (int p = 0; p < 2; p++) {
        bfs_init_kernel<<<nbI, T>>>(perms[p], n);
        for (int it = 0; it < MAX_ITERS; ++it) {
            bfs_relax_kernel<<<nbN, T>>>(perms[p], n);
            bfs_step_kernel<<<1, 1>>>(n, k);
        }
        hist_kernel<<<nbN, T>>>(n);
        find_hstar_kernel<<<1, 1024>>>(k);
        find_pstar_kernel<<<1, 1024>>>(n);
        keep_kernel<<<nbN, T>>>(perms[p], n);
        masked_gcn_kernel<<<gStride, 256>>>(feat, Wenc, n);
        compute_v_kernel<<<1, 64>>>(Wdisc, p, k);
    }

    loss_kernel<<<gStride, 256>>>(n);
    finalize_kernel<<<1, 1>>>((float*)d_out, n);
}

// round 4
// speedup vs baseline: 2.6283x; 2.6283x over previous
#include <cuda_runtime.h>
#include <math.h>

// ============================================================================
// DGISubgraphCL — 8-launch persistent-kernel pipeline.
// Inputs: feat[N,64] f32, W_enc[64,64] f32, W_disc[64,64] f32,
//   src[E] i32, dst[E] i32, perm_neg[N] i32, perm1[N] i32, perm2[N] i32.
// Output: scalar f32 loss.
// ============================================================================

#define N_MAX 131072
#define E_MAX (N_MAX * 17)
#define HIST_BINS 15001
#define PB 132           // persistent blocks (<= SM count, 1 block/SM at 1024 thr)
#define PT 1024          // persistent threads per block

// ---- device scratch (allocation-free rule: __device__ globals) ----
__device__ int g_rowptr[N_MAX + 1];
__device__ int g_cnt[N_MAX];
__device__ int g_cursor[N_MAX];
__device__ int g_colidx[E_MAX];
__device__ int g_hop[2][N_MAX];
__device__ int g_invperm[N_MAX];
__device__ unsigned char g_keep1[N_MAX];
__device__ unsigned char g_keep2[N_MAX];
__device__ int g_hist[HIST_BINS];
__device__ float g_hpos[N_MAX * 64];
__device__ float g_hneg[N_MAX * 64];
__device__ double g_summary[128];   // [2][64] flat
__device__ float g_v[2][64];
__device__ double g_loss[4];

__device__ int g_blocksum[PB];
__device__ int g_blockoff[PB];
__device__ int g_blkCnt[PB];

// BFS / selection control state
__device__ int g_cur, g_done, g_hc, g_cntPrev;
__device__ int g_cntAcc;
__device__ unsigned long long g_seedkey;
__device__ int g_hstar, g_rrem, g_pstar, g_pselBlock, g_pselRem;

// software grid barrier (monotonic counter; reset at kernel exit)
__device__ unsigned int g_barArrive = 0;

// ============================================================================
// helpers
// ============================================================================

__device__ __forceinline__ void grid_sync(unsigned& epoch) {
    __syncthreads();
    if (threadIdx.x == 0) {
        __threadfence();
        unsigned target = (epoch + 1) * gridDim.x;
        atomicAdd(&g_barArrive, 1u);
        while (*((volatile unsigned*)&g_barArrive) < target) {}
        __threadfence();
    }
    epoch++;
    __syncthreads();
}

__device__ __forceinline__ void grid_exit_reset(unsigned epoch) {
    __syncthreads();
    if (threadIdx.x == 0) {
        __threadfence();
        unsigned target = (epoch + 1) * gridDim.x;
        unsigned p = atomicAdd(&g_barArrive, 1u) + 1;
        if (p == target) g_barArrive = 0;  // last arriver resets; nobody waits here
    }
}

__device__ __forceinline__ float softplusf(float x) {
    return fmaxf(x, 0.f) + log1pf(expf(-fabsf(x)));
}

__device__ __forceinline__ unsigned long long ullmin2(unsigned long long a, unsigned long long b) {
    return a < b ? a : b;
}

// inclusive block scan, blockDim.x == 1024 required
__device__ __forceinline__ int blockScanInc(int v, int* sWarp) {
    int lane = threadIdx.x & 31;
    int wid = threadIdx.x >> 5;
#pragma unroll
    for (int off = 1; off < 32; off <<= 1) {
        int t = __shfl_up_sync(0xffffffffu, v, off);
        if (lane >= off) v += t;
    }
    if (lane == 31) sWarp[wid] = v;
    __syncthreads();
    if (wid == 0) {
        int w = sWarp[lane];
#pragma unroll
        for (int off = 1; off < 32; off <<= 1) {
            int t = __shfl_up_sync(0xffffffffu, w, off);
            if (lane >= off) w += t;
        }
        sWarp[lane] = w;
    }
    __syncthreads();
    return v + (wid ? sWarp[wid - 1] : 0);
}

// ============================================================================
// Kernel 1: persistent CSR build (zero + count + scan + scatter)
// ============================================================================

__global__ __launch_bounds__(PT, 1)
void csr_kernel(const int* __restrict__ src, const int* __restrict__ dst, int e, int n) {
    unsigned epoch = 0;
    int gtid = blockIdx.x * PT + threadIdx.x;
    int gsz = gridDim.x * PT;
    int chunk = (n + gridDim.x - 1) / gridDim.x;
    int b0 = blockIdx.x * chunk;
    int b1 = min(b0 + chunk, n);

    // phase 0: zero everything
    for (int i = gtid; i < n; i += gsz) { g_cnt[i] = 0; g_cursor[i] = 0; }
    if (gtid < 4) g_loss[gtid] = 0.0;
    if (gtid < 128) g_summary[gtid] = 0.0;
    if (gtid == 0) g_rowptr[n] = e;
    grid_sync(epoch);

    // phase 1: count in-degrees
    for (int i = gtid; i < e; i += gsz) atomicAdd(&g_cnt[dst[i]], 1);
    grid_sync(epoch);

    // phase 2: per-block local exclusive scan
    __shared__ int sWarp[32];
    __shared__ int sRun, sTot;
    if (threadIdx.x == 0) sRun = 0;
    __syncthreads();
    for (int base = b0; base < b1; base += PT) {
        int i = base + threadIdx.x;
        int v = (i < b1) ? __ldcg(&g_cnt[i]) : 0;
        int incl = blockScanInc(v, sWarp);
        if (i < b1) g_rowptr[i] = sRun + incl - v;
        if (threadIdx.x == PT - 1) sTot = incl;
        __syncthreads();
        if (threadIdx.x == 0) sRun += sTot;
        __syncthreads();
    }
    if (threadIdx.x == 0) g_blocksum[blockIdx.x] = sRun;
    grid_sync(epoch);

    // phase 3: block 0 scans block sums
    if (blockIdx.x == 0) {
        int b = threadIdx.x;
        int v = (b < (int)gridDim.x) ? __ldcg(&g_blocksum[b]) : 0;
        int incl = blockScanInc(v, sWarp);
        if (b < (int)gridDim.x) g_blockoff[b] = incl - v;
    }
    grid_sync(epoch);

    // phase 4: add block offsets
    {
        int off = __ldcg(&g_blockoff[blockIdx.x]);
        for (int i = b0 + threadIdx.x; i < b1; i += PT)
            g_rowptr[i] = __ldcg(&g_rowptr[i]) + off;
    }
    grid_sync(epoch);

    // phase 5: scatter edges by dst
    for (int i = gtid; i < e; i += gsz) {
        int d = dst[i];
        int p = atomicAdd(&g_cursor[d], 1);
        g_colidx[__ldcg(&g_rowptr[d]) + p] = src[i];
    }
    grid_exit_reset(epoch);
}

// ============================================================================
// Kernel 2: fused pos + neg GCN (one colidx pass, two feat gathers per edge)
// ============================================================================

__global__ __launch_bounds__(256)
void gcn_fused_kernel(const float* __restrict__ feat, const float* __restrict__ Wenc,
                      const int* __restrict__ permneg, int n) {
    __shared__ float sW[4096];
    __shared__ float sxp[8][64];
    __shared__ float sxn[8][64];
    int tid = threadIdx.x;
    for (int j = tid; j < 4096; j += 256) sW[j] = Wenc[j];
    __syncthreads();
    int warp = tid >> 5, lane = tid & 31;
    for (int node = blockIdx.x * 8 + warp; node < n; node += gridDim.x * 8) {
        int s0 = g_rowptr[node], s1 = g_rowptr[node + 1];
        float ap0 = 0.f, ap1 = 0.f, an0 = 0.f, an1 = 0.f;
        for (int e2 = s0; e2 < s1; e2++) {
            int s = g_colidx[e2];
            int r = permneg[s];
            float2 fp = *reinterpret_cast<const float2*>(feat + (size_t)s * 64 + 2 * lane);
            float2 fn = *reinterpret_cast<const float2*>(feat + (size_t)r * 64 + 2 * lane);
            ap0 += fp.x; ap1 += fp.y; an0 += fn.x; an1 += fn.y;
        }
        float invd = 1.f / (float)max(s1 - s0, 1);
        sxp[warp][2 * lane] = ap0 * invd; sxp[warp][2 * lane + 1] = ap1 * invd;
        sxn[warp][2 * lane] = an0 * invd; sxn[warp][2 * lane + 1] = an1 * invd;
        __syncwarp();
        float op0 = 0.f, op1 = 0.f, on0 = 0.f, on1 = 0.f;
#pragma unroll
        for (int kk = 0; kk < 64; kk++) {
            float w0 = sW[kk * 64 + 2 * lane], w1 = sW[kk * 64 + 2 * lane + 1];
            float xp = sxp[warp][kk], xn = sxn[warp][kk];
            op0 += xp * w0; op1 += xp * w1; on0 += xn * w0; on1 += xn * w1;
        }
        *reinterpret_cast<float2*>(g_hpos + (size_t)node * 64 + 2 * lane) =
            make_float2(fmaxf(op0, 0.f), fmaxf(op1, 0.f));
        *reinterpret_cast<float2*>(g_hneg + (size_t)node * 64 + 2 * lane) =
            make_float2(fmaxf(on0, 0.f), fmaxf(on1, 0.f));
        __syncwarp();
    }
}

// ============================================================================
// Kernel 3/4: persistent BFS + exact top-k selection (one launch per perm)
// ============================================================================

__global__ __launch_bounds__(PT, 1)
void bfs_kernel(const int* __restrict__ perm, int n, int k, int which) {
    unsigned epoch = 0;
    int gtid = blockIdx.x * PT + threadIdx.x;
    int gsz = gridDim.x * PT;
    unsigned char* keep = which ? g_keep2 : g_keep1;

    // init
    int root = __ldg(&perm[0]);
    for (int i = gtid; i < n; i += gsz) {
        __stcg(&g_hop[0][i], (i == root) ? 0 : n);
        __stcg(&g_invperm[perm[i]], i);
    }
    for (int i = gtid; i < HIST_BINS; i += gsz) __stcg(&g_hist[i], 0);
    if (gtid == 0) {
        g_cur = 0; g_done = 0; g_hc = 0; g_cntPrev = 1;
        atomicExch(&g_cntAcc, 0);
        atomicExch(&g_seedkey, ~0ull);
    }
    grid_sync(epoch);

    __shared__ int sR[32];
    __shared__ unsigned long long sK[32];
    __shared__ int sWarp[32];

    // relax loop: exact replica of the reference while-loop semantics
    int guard = 0;
    while (!(*(volatile int*)&g_done)) {
        if (++guard > n + 8) break;
        int cur = *(volatile int*)&g_cur;
        const int* ho = g_hop[cur];
        int* hn = g_hop[cur ^ 1];
        int reached = 0;
        unsigned long long key = ~0ull;
        for (int i = gtid; i < n; i += gsz) {
            int h = __ldcg(&ho[i]);
            int s0 = g_rowptr[i], s1 = g_rowptr[i + 1];
#pragma unroll 4
            for (int e2 = s0; e2 < s1; e2++) {
                int s = g_colidx[e2];
                int c = __ldcg(&ho[s]) + (s != i);  // self-loop weight 0
                h = min(h, c);
            }
            __stcg(&hn[i], h);
            if (h < n) reached++;
            else key = ullmin2(key, ((unsigned long long)(unsigned)perm[i] << 32) | (unsigned)i);
        }
#pragma unroll
        for (int off = 16; off; off >>= 1) {
            reached += __shfl_down_sync(0xffffffffu, reached, off);
            key = ullmin2(key, __shfl_down_sync(0xffffffffu, key, off));
        }
        int wid = threadIdx.x >> 5, lane = threadIdx.x & 31;
        if (lane == 0) { sR[wid] = reached; sK[wid] = key; }
        __syncthreads();
        if (threadIdx.x < 32) {
            int r = sR[threadIdx.x];
            unsigned long long kk2 = sK[threadIdx.x];
#pragma unroll
            for (int off = 16; off; off >>= 1) {
                r += __shfl_down_sync(0xffffffffu, r, off);
                kk2 = ullmin2(kk2, __shfl_down_sync(0xffffffffu, kk2, off));
            }
            if (threadIdx.x == 0) {
                if (r) atomicAdd(&g_cntAcc, r);
                if (kk2 != ~0ull) atomicMin(&g_seedkey, kk2);
            }
        }
        grid_sync(epoch);
        if (blockIdx.x == 0 && threadIdx.x == 0) {
            int hc = g_hc + 1; g_hc = hc;
            int nc = g_cur ^ 1;
            int cnt = atomicAdd(&g_cntAcc, 0);
            if (cnt == g_cntPrev) {                   // stuck -> seed smallest-perm unreached
                unsigned long long kv = atomicAdd(&g_seedkey, 0ull);
                if (kv != ~0ull) {
                    int idx = (int)(unsigned)(kv & 0xffffffffull);
                    __stcg(&g_hop[nc][idx], hc);
                    cnt++;
                }
            }
            g_cntPrev = cnt;
            g_cur = nc;
            atomicExch(&g_cntAcc, 0);
            atomicExch(&g_seedkey, ~0ull);
            if (cnt > k) g_done = 1;
        }
        grid_sync(epoch);
    }

    int fcur = *(volatile int*)&g_cur;
    const int* hop = g_hop[fcur];

    // histogram of clipped hops
    {
        __shared__ int sh[256];
        for (int j = threadIdx.x; j < 256; j += PT) sh[j] = 0;
        __syncthreads();
        for (int i = gtid; i < n; i += gsz) {
            int hv = min(__ldcg(&hop[i]), 15000);
            if (hv < 256) atomicAdd(&sh[hv], 1);
            else atomicAdd(&g_hist[hv], 1);
        }
        __syncthreads();
        for (int j = threadIdx.x; j < 256; j += PT)
            if (sh[j]) atomicAdd(&g_hist[j], sh[j]);
    }
    grid_sync(epoch);

    // hstar: smallest hop whose cumulative count reaches k
    if (blockIdx.x == 0) {
        __shared__ int sRun, sTot, sDone;
        if (threadIdx.x == 0) { sRun = 0; sDone = 0; }
        __syncthreads();
        for (int base = 0; base < HIST_BINS; base += PT) {
            if (sDone) break;
            int h = base + threadIdx.x;
            int v = (h < HIST_BINS) ? __ldcg(&g_hist[h]) : 0;
            int incl = blockScanInc(v, sWarp);
            int P = sRun + incl;
            if (v > 0 && P >= k && P - v < k) { g_hstar = h; g_rrem = k - (P - v); sDone = 1; }
            if (threadIdx.x == PT - 1) sTot = incl;
            __syncthreads();
            if (threadIdx.x == 0) sRun += sTot;
            __syncthreads();
        }
    }
    grid_sync(epoch);
    int hstar = *(volatile int*)&g_hstar;
    int rrem = *(volatile int*)&g_rrem;

    // pstar: rrem-th smallest perm value among hop==hstar (grid-parallel rank-select)
    int chunk = (n + gridDim.x - 1) / gridDim.x;
    int v0 = blockIdx.x * chunk, v1 = min(v0 + chunk, n);
    {
        int cnt = 0;
        for (int v = v0 + threadIdx.x; v < v1; v += PT) {
            int j = __ldcg(&g_invperm[v]);
            cnt += (min(__ldcg(&hop[j]), 15000) == hstar);
        }
#pragma unroll
        for (int off = 16; off; off >>= 1) cnt += __shfl_down_sync(0xffffffffu, cnt, off);
        int wid = threadIdx.x >> 5, lane = threadIdx.x & 31;
        if (lane == 0) sR[wid] = cnt;
        __syncthreads();
        if (threadIdx.x < 32) {
            int r = sR[threadIdx.x];
#pragma unroll
            for (int off = 16; off; off >>= 1) r += __shfl_down_sync(0xffffffffu, r, off);
            if (threadIdx.x == 0) g_blkCnt[blockIdx.x] = r;
        }
    }
    grid_sync(epoch);
    if (blockIdx.x == 0) {
        int b = threadIdx.x;
        int v = (b < (int)gridDim.x) ? __ldcg(&g_blkCnt[b]) : 0;
        int incl = blockScanInc(v, sWarp);
        int excl = incl - v;
        if (b < (int)gridDim.x && v > 0 && excl < rrem && rrem <= incl) {
            g_pselBlock = b; g_pselRem = rrem - excl;
        }
    }
    grid_sync(epoch);
    if ((int)blockIdx.x == *(volatile int*)&g_pselBlock) {
        int rem = *(volatile int*)&g_pselRem;
        __shared__ int sRun2, sTot2, sDone2;
        if (threadIdx.x == 0) { sRun2 = 0; sDone2 = 0; }
        __syncthreads();
        for (int base = v0; base < v1; base += PT) {
            if (sDone2) break;
            int v = base + threadIdx.x;
            int pred = 0;
            if (v < v1) {
                int j = __ldcg(&g_invperm[v]);
                pred = (min(__ldcg(&hop[j]), 15000) == hstar);
            }
            int incl = blockScanInc(pred, sWarp);
            int cum = sRun2 + incl;
            if (pred && cum == rem) { g_pstar = v; sDone2 = 1; }
            if (threadIdx.x == PT - 1) sTot2 = incl;
            __syncthreads();
            if (threadIdx.x == 0) sRun2 += sTot2;
            __syncthreads();
        }
    }
    grid_sync(epoch);
    int pstar = *(volatile int*)&g_pstar;
    for (int i = gtid; i < n; i += gsz) {
        int hv = min(__ldcg(&hop[i]), 15000);
        keep[i] = (hv < hstar) || (hv == hstar && perm[i] <= pstar);
    }
    grid_exit_reset(epoch);
}

// ============================================================================
// Kernel 5: fused masked GCN for BOTH perms, one gather pass, block-staged sums
// ============================================================================

__global__ __launch_bounds__(256)
void masked_gcn_kernel(const float* __restrict__ feat, const float* __restrict__ Wenc, int n) {
    __shared__ float sW[4096];
    __shared__ float sx1[8][64];
    __shared__ float sx2[8][64];
    __shared__ double sSum[128];
    int tid = threadIdx.x;
    for (int j = tid; j < 4096; j += 256) sW[j] = Wenc[j];
    if (tid < 128) sSum[tid] = 0.0;
    __syncthreads();
    int warp = tid >> 5, lane = tid & 31;
    double a10 = 0.0, a11 = 0.0, a20 = 0.0, a21 = 0.0;
    for (int node = blockIdx.x * 8 + warp; node < n; node += gridDim.x * 8) {
        int k1d = g_keep1[node], k2d = g_keep2[node];
        if (!(k1d | k2d)) continue;
        int s0 = g_rowptr[node], s1 = g_rowptr[node + 1];
        float b10 = 0.f, b11 = 0.f, b20 = 0.f, b21 = 0.f;
        int c1 = 0, c2 = 0;
        for (int e2 = s0; e2 < s1; e2++) {
            int s = g_colidx[e2];
            int k1 = k1d & (int)g_keep1[s];
            int k2 = k2d & (int)g_keep2[s];
            if (k1 | k2) {
                float2 f = *reinterpret_cast<const float2*>(feat + (size_t)s * 64 + 2 * lane);
                if (k1) { b10 += f.x; b11 += f.y; c1++; }
                if (k2) { b20 += f.x; b21 += f.y; c2++; }
            }
        }
        if (k1d) {
            float inv1 = 1.f / (float)max(c1, 1);
            sx1[warp][2 * lane] = b10 * inv1; sx1[warp][2 * lane + 1] = b11 * inv1;
        }
        if (k2d) {
            float inv2 = 1.f / (float)max(c2, 1);
            sx2[warp][2 * lane] = b20 * inv2; sx2[warp][2 * lane + 1] = b21 * inv2;
        }
        __syncwarp();
        float o10 = 0.f, o11 = 0.f, o20 = 0.f, o21 = 0.f;
#pragma unroll
        for (int kk = 0; kk < 64; kk++) {
            float w0 = sW[kk * 64 + 2 * lane], w1 = sW[kk * 64 + 2 * lane + 1];
            if (k1d) { float x = sx1[warp][kk]; o10 += x * w0; o11 += x * w1; }
            if (k2d) { float x = sx2[warp][kk]; o20 += x * w0; o21 += x * w1; }
        }
        if (k1d) { a10 += (double)fmaxf(o10, 0.f); a11 += (double)fmaxf(o11, 0.f); }
        if (k2d) { a20 += (double)fmaxf(o20, 0.f); a21 += (double)fmaxf(o21, 0.f); }
        __syncwarp();
    }
    // block-level staging, then 1 global atomic per column per block
    atomicAdd(&sSum[2 * lane], a10);
    atomicAdd(&sSum[2 * lane + 1], a11);
    atomicAdd(&sSum[64 + 2 * lane], a20);
    atomicAdd(&sSum[64 + 2 * lane + 1], a21);
    __syncthreads();
    if (tid < 128) {
        double v = sSum[tid];
        if (v != 0.0) atomicAdd(&g_summary[tid], v);
    }
}

// ============================================================================
// Kernel 6: v = W_disc @ sigmoid(summary/k) for both perms
// ============================================================================

__global__ void compute_v_kernel(const float* __restrict__ Wdisc, int k) {
    __shared__ float ss[2][64];
    int tid = threadIdx.x;  // 128 threads
    int p = tid >> 6, c = tid & 63;
    double s = g_summary[tid] / (double)k;
    ss[p][c] = (float)(1.0 / (1.0 + exp(-s)));
    __syncthreads();
    float v = 0.f;
#pragma unroll
    for (int b = 0; b < 64; b++) v += Wdisc[c * 64 + b] * ss[p][b];
    g_v[p][c] = v;
}

// ============================================================================
// Kernel 7: BCE losses for both perms in one pass over h_pos / h_neg
// ============================================================================

__global__ __launch_bounds__(256)
void loss_kernel(int n) {
    __shared__ float sv0[64], sv1[64];
    __shared__ double sL[4];
    int tid = threadIdx.x;
    if (tid < 64) { sv0[tid] = g_v[0][tid]; sv1[tid] = g_v[1][tid]; }
    if (tid < 4) sL[tid] = 0.0;
    __syncthreads();
    int warp = tid >> 5, lane = tid & 31;
    float v00 = sv0[2 * lane], v01 = sv0[2 * lane + 1];
    float v10 = sv1[2 * lane], v11 = sv1[2 * lane + 1];
    double l0 = 0, l1 = 0, l2 = 0, l3 = 0;
    for (int node = blockIdx.x * 8 + warp; node < n; node += gridDim.x * 8) {
        float2 hp = *reinterpret_cast<const float2*>(g_hpos + (size_t)node * 64 + 2 * lane);
        float2 hn = *reinterpret_cast<const float2*>(g_hneg + (size_t)node * 64 + 2 * lane);
        float p1 = hp.x * v00 + hp.y * v01;
        float p2 = hp.x * v10 + hp.y * v11;
        float q1 = hn.x * v00 + hn.y * v01;
        float q2 = hn.x * v10 + hn.y * v11;
#pragma unroll
        for (int off = 16; off; off >>= 1) {
            p1 += __shfl_down_sync(0xffffffffu, p1, off);
            p2 += __shfl_down_sync(0xffffffffu, p2, off);
            q1 += __shfl_down_sync(0xffffffffu, q1, off);
            q2 += __shfl_down_sync(0xffffffffu, q2, off);
        }
        if (lane == 0) {
            l0 += (double)softplusf(-p1);
            l1 += (double)softplusf(q1);
            l2 += (double)softplusf(-p2);
            l3 += (double)softplusf(q2);
        }
    }
    if (lane == 0) {
        atomicAdd(&sL[0], l0); atomicAdd(&sL[1], l1);
        atomicAdd(&sL[2], l2); atomicAdd(&sL[3], l3);
    }
    __syncthreads();
    if (tid < 4) atomicAdd(&g_loss[tid], sL[tid]);
}

__global__ void finalize_kernel(float* out, int n) {
    out[0] = (float)((g_loss[0] + g_loss[1] + g_loss[2] + g_loss[3]) / (double)n);
}

// ============================================================================
// launch
// ============================================================================

extern "C" void kernel_launch(void* const* d_in, const int* in_sizes, int n_in,
                              void* d_out, int out_size) {
    const float* feat = (const float*)d_in[0];
    const float* Wenc = (const float*)d_in[1];
    const float* Wdisc = (const float*)d_in[2];
    const int* src = (const int*)d_in[3];
    const int* dst = (const int*)d_in[4];
    const int* permneg = (const int*)d_in[5];
    const int* perm1 = (const int*)d_in[6];
    const int* perm2 = (const int*)d_in[7];

    int e = in_sizes[3];
    int n = in_sizes[5];
    int k = (int)((double)n * 0.8);

    csr_kernel<<<PB, PT>>>(src, dst, e, n);

    int gB = (n + 7) / 8;
    int gGrid = gB < 2960 ? gB : 2960;
    gcn_fused_kernel<<<gGrid, 256>>>(feat, Wenc, permneg, n);

    bfs_kernel<<<PB, PT>>>(perm1, n, k, 0);
    bfs_kernel<<<PB, PT>>>(perm2, n, k, 1);

    masked_gcn_kernel<<<(gGrid < 1480 ? gGrid : 1480), 256>>>(feat, Wenc, n);
    compute_v_kernel<<<1, 128>>>(Wdisc, k);
    loss_kernel<<<(gGrid < 1480 ? gGrid : 1480), 256>>>(n);
    finalize_kernel<<<1, 1>>>((float*)d_out, n);
}